// round 2
// baseline (speedup 1.0000x reference)
#include <cuda_runtime.h>
#include <cuda_bf16.h>
#include <cstdint>

// ============================================================================
// AlignmentContrastiveLoss — bf16 mma.sync GEMM + fused masked max/sum epilogue
// (sm_100 baseline ISA only: NO tcgen05/TMA — those need the 'a' target which
//  this harness's compute_100 PTX pass rejects.)
//
// Stage 1 (pack):  A[64][128][1024] bf16  rows 0-35 = im[2p][1+i], 36-71 = im[2p+1][1+i], rest 0
//                  B[128][64][1024] bf16  rows 0-49 = s[c][1+j], rest 0
// Stage 2 (mma):   grid (64,64): CTA computes D[128][128] = Apair @ Bpair^T
//                  (two c's of 64 rows each), K=1024, bf16 x bf16 -> f32,
//                  2-stage cp.async pipeline, fused masked max/sum -> S[b][c]
// Stage 3 (loss):  hinge-loss double sum over S
// ============================================================================

static constexpr int NB  = 128;
static constexpr int DIM = 1024;
static constexpr int AP_ELEMS = 64 * 128 * DIM;
static constexpr int BP_ELEMS = 128 * 64 * DIM;

__device__ __align__(16) __nv_bfloat16 g_A[AP_ELEMS];
__device__ __align__(16) __nv_bfloat16 g_B[BP_ELEMS];
__device__ float g_S[NB * NB];

// ---------------------------------------------------------------------------
__device__ __forceinline__ uint32_t smem_u32(const void* p) {
    uint32_t a;
    asm("{ .reg .u64 t; cvta.to.shared.u64 t, %1; cvt.u32.u64 %0, t; }" : "=r"(a) : "l"(p));
    return a;
}
__device__ __forceinline__ void cpa16(uint32_t dst, const void* src) {
    asm volatile("cp.async.cg.shared.global [%0], [%1], 16;" :: "r"(dst), "l"(src));
}
#define CPA_COMMIT() asm volatile("cp.async.commit_group;" ::: "memory")
#define CPA_WAIT1()  asm volatile("cp.async.wait_group 1;" ::: "memory")
#define CPA_WAIT0()  asm volatile("cp.async.wait_group 0;" ::: "memory")

__device__ __forceinline__ uint32_t lds32(uint32_t a) {
    uint32_t v;
    asm volatile("ld.shared.b32 %0, [%1];" : "=r"(v) : "r"(a));
    return v;
}
__device__ __forceinline__ void mma_bf16(float& d0, float& d1, float& d2, float& d3,
                                         uint32_t a0, uint32_t a1, uint32_t a2, uint32_t a3,
                                         uint32_t b0, uint32_t b1) {
    asm volatile(
        "mma.sync.aligned.m16n8k16.row.col.f32.bf16.bf16.f32 "
        "{%0,%1,%2,%3}, {%4,%5,%6,%7}, {%8,%9}, {%0,%1,%2,%3};"
        : "+f"(d0), "+f"(d1), "+f"(d2), "+f"(d3)
        : "r"(a0), "r"(a1), "r"(a2), "r"(a3), "r"(b0), "r"(b1));
}

// ---------------------------------------------------------------------------
// Stage 1: pack fp32 -> bf16 with slicing + zero padding
// ---------------------------------------------------------------------------
__global__ void pack_kernel(const float* __restrict__ im, const float* __restrict__ sq) {
    const int total = AP_ELEMS + BP_ELEMS;  // 16777216
    for (int idx = blockIdx.x * blockDim.x + threadIdx.x; idx < total;
         idx += gridDim.x * blockDim.x) {
        if (idx < AP_ELEMS) {
            int k = idx & 1023;
            int row = (idx >> 10) & 127;
            int pr = idx >> 17;
            float v = 0.f;
            if (row < 72) {
                int b = pr * 2 + (row >= 36);
                int i = (row < 36) ? row : row - 36;
                v = im[(size_t)(b * 37 + i + 1) * 1024 + k];
            }
            g_A[idx] = __float2bfloat16(v);
        } else {
            int j = idx - AP_ELEMS;
            int k = j & 1023;
            int row = (j >> 10) & 63;
            int c = j >> 16;
            float v = 0.f;
            if (row < 50) v = sq[(size_t)(c * 53 + row + 1) * 1024 + k];
            g_B[j] = __float2bfloat16(v);
        }
    }
}

// ---------------------------------------------------------------------------
// Stage 2: mma.sync GEMM + fused epilogue
// ---------------------------------------------------------------------------
// smem layout (static, 41 KB):
//   stage s in {0,1}: A_s at s*20480        (128 rows x 40 bf16, rows padded: 32 data + 8 pad)
//                     B_s at s*20480+10240  (128 rows x 40 bf16)
//   pairS (4 floats)  at 40960
//   epilogue redbuf [72][132] f32 aliases offset 0 (38016 B)
static constexpr int STAGE_BYTES = 20480;
static constexpr int ROW_BYTES   = 80;    // 40 bf16
static constexpr int SM_PAIRS    = 40960;
static constexpr int NCH = 32;            // K chunks of 32

__global__ __launch_bounds__(256, 1)
void mma_kernel(const int* __restrict__ im_len, const int* __restrict__ s_len) {
    __shared__ __align__(16) char sm[41088];
    const uint32_t sb = smem_u32(sm);
    const int tid  = threadIdx.x;
    const int lane = tid & 31;
    const int wid  = tid >> 5;
    const int p = blockIdx.x;   // b pair {2p, 2p+1}
    const int g = blockIdx.y;   // c pair {2g, 2g+1}

    const __nv_bfloat16* Ap = g_A + (size_t)p * (128 * DIM);
    const __nv_bfloat16* Bp = g_B + (size_t)(2 * g) * (64 * DIM); // 128 contiguous rows

    // per-thread load mapping: 4 x 16B transfers per stage
    const int t0 = tid;             // 0..255
    // t = t0 + it*256, it=0..3 -> 1024 transfers: first 512 A, next 512 B
    auto load_stage = [&](int stage, int chunk) {
        const int k0 = chunk * 32;
        #pragma unroll
        for (int it = 0; it < 4; ++it) {
            int t = t0 + it * 256;
            if (t < 512) {
                int row = t >> 2, seg = t & 3;
                cpa16(sb + stage * STAGE_BYTES + row * ROW_BYTES + seg * 16,
                      Ap + row * DIM + k0 + seg * 8);
            } else {
                int u = t - 512;
                int row = u >> 2, seg = u & 3;
                cpa16(sb + stage * STAGE_BYTES + 10240 + row * ROW_BYTES + seg * 16,
                      Bp + row * DIM + k0 + seg * 8);
            }
        }
    };

    // warp layout: 4 (m) x 2 (n); warp tile 32 x 64
    const int wm = wid >> 1;          // 0..3
    const int wn = wid & 1;           // 0..1
    const int group = lane >> 2;      // 0..7
    const int tig   = lane & 3;       // 0..3
    const int mbase = wm * 32;
    const int nbase = wn * 64;

    float acc[2][8][4];
    #pragma unroll
    for (int mi = 0; mi < 2; ++mi)
        #pragma unroll
        for (int ni = 0; ni < 8; ++ni)
            #pragma unroll
            for (int q = 0; q < 4; ++q) acc[mi][ni][q] = 0.f;

    load_stage(0, 0); CPA_COMMIT();
    load_stage(1, 1); CPA_COMMIT();

    for (int ch = 0; ch < NCH; ++ch) {
        CPA_WAIT1();
        __syncthreads();
        const uint32_t As = sb + (ch & 1) * STAGE_BYTES;
        const uint32_t Bs = As + 10240;
        #pragma unroll
        for (int kk = 0; kk < 2; ++kk) {
            const uint32_t kb = kk * 32;  // 16 bf16 = 32 bytes
            uint32_t a[2][4];
            #pragma unroll
            for (int mi = 0; mi < 2; ++mi) {
                uint32_t r0 = As + (mbase + mi * 16 + group) * ROW_BYTES + kb + tig * 4;
                uint32_t r1 = r0 + 8 * ROW_BYTES;
                a[mi][0] = lds32(r0);
                a[mi][1] = lds32(r1);
                a[mi][2] = lds32(r0 + 16);
                a[mi][3] = lds32(r1 + 16);
            }
            #pragma unroll
            for (int ni = 0; ni < 8; ++ni) {
                uint32_t rb = Bs + (nbase + ni * 8 + group) * ROW_BYTES + kb + tig * 4;
                uint32_t b0 = lds32(rb);
                uint32_t b1 = lds32(rb + 16);
                #pragma unroll
                for (int mi = 0; mi < 2; ++mi)
                    mma_bf16(acc[mi][ni][0], acc[mi][ni][1], acc[mi][ni][2], acc[mi][ni][3],
                             a[mi][0], a[mi][1], a[mi][2], a[mi][3], b0, b1);
            }
        }
        __syncthreads();
        if (ch + 2 < NCH) load_stage(ch & 1, ch + 2);
        CPA_COMMIT();
    }
    CPA_WAIT0();
    __syncthreads();

    // ---------------- epilogue ----------------
    float* red   = reinterpret_cast<float*>(sm);              // [72][132]
    float* pairS = reinterpret_cast<float*>(sm + SM_PAIRS);   // [4]: (bhalf, chalf)

    if (tid < 4) pairS[tid] = 0.f;

    // row validity for this thread's 4 row positions
    const int iml0 = im_len[2 * p] - 1;
    const int iml1 = im_len[2 * p + 1] - 1;
    #pragma unroll
    for (int mi = 0; mi < 2; ++mi) {
        #pragma unroll
        for (int half = 0; half < 2; ++half) {
            int r = mbase + mi * 16 + group + half * 8;
            bool valid = false;
            if (r < 72) {
                int i = (r < 36) ? r : r - 36;
                valid = i < ((r < 36) ? iml0 : iml1);
            }
            if (r < 72) {
                #pragma unroll
                for (int ni = 0; ni < 8; ++ni) {
                    int col = nbase + ni * 8 + tig * 2;
                    float v0 = valid ? acc[mi][ni][half * 2 + 0] : 0.f;
                    float v1 = valid ? acc[mi][ni][half * 2 + 1] : 0.f;
                    red[r * 132 + col]     = v0;
                    red[r * 132 + col + 1] = v1;
                }
            }
        }
    }
    __syncthreads();

    // 200 reductions: (chalf 2) x (bhalf 2) x (j 50), each max over 36 rows
    if (tid < 200) {
        int cc   = tid / 100;
        int rem  = tid % 100;
        int half = rem / 50;
        int jj   = rem % 50;
        int c = 2 * g + cc;
        int sl = s_len[c] - 3;
        if (jj < sl) {
            const float* col = red + (half * 36) * 132 + cc * 64 + jj;
            float m = col[0];
            #pragma unroll
            for (int rr = 1; rr < 36; ++rr) m = fmaxf(m, col[rr * 132]);
            atomicAdd(&pairS[half * 2 + cc], m);
        }
    }
    __syncthreads();
    if (tid < 4) {
        int half = tid >> 1, cc = tid & 1;
        g_S[(2 * p + half) * NB + (2 * g + cc)] = pairS[tid];
    }
}

// ---------------------------------------------------------------------------
// Stage 3: hinge-loss reduction over S (128x128)
// ---------------------------------------------------------------------------
__global__ void loss_kernel(float* __restrict__ out) {
    __shared__ float diag[NB];
    __shared__ float wsum[8];
    const int tid = threadIdx.x;
    if (tid < NB) diag[tid] = g_S[tid * (NB + 1)];
    __syncthreads();
    float acc = 0.f;
    for (int idx = tid; idx < NB * NB; idx += 256) {
        int b = idx >> 7, c = idx & 127;
        if (b != c) {
            float sc = g_S[idx];
            acc += fmaxf(0.f, 0.2f + sc - diag[b]) + fmaxf(0.f, 0.2f + sc - diag[c]);
        }
    }
    #pragma unroll
    for (int o = 16; o; o >>= 1) acc += __shfl_xor_sync(0xffffffffu, acc, o);
    if ((tid & 31) == 0) wsum[tid >> 5] = acc;
    __syncthreads();
    if (tid < 8) {
        float v = wsum[tid];
        #pragma unroll
        for (int o = 4; o; o >>= 1) v += __shfl_xor_sync(0xffu, v, o);
        if (tid == 0) out[0] = v;
    }
}

// ---------------------------------------------------------------------------
extern "C" void kernel_launch(void* const* d_in, const int* in_sizes, int n_in,
                              void* d_out, int out_size) {
    (void)in_sizes; (void)n_in; (void)out_size;
    const float* im   = (const float*)d_in[0];
    const float* sq   = (const float*)d_in[1];
    const int* im_len = (const int*)d_in[2];
    const int* s_len  = (const int*)d_in[3];

    pack_kernel<<<65536, 256>>>(im, sq);
    mma_kernel<<<dim3(64, 64), 256>>>(im_len, s_len);
    loss_kernel<<<1, 256>>>((float*)d_out);
}

// round 4
// speedup vs baseline: 1.9063x; 1.9063x over previous
#include <cuda_runtime.h>
#include <cuda_bf16.h>
#include <cstdint>

// ============================================================================
// AlignmentContrastiveLoss — dense-packed bf16 mma.sync GEMM + fused epilogue
//
// Dense packing removes zero-padding waste (R2: 137 GFLOP padded -> 61.6):
//   A[4608][1024]  row r -> b = r/36, i = r%36,  value im[b][i+1][:]
//   B[6528][1024]  row r -> c = r/50, j = r%50,  value s[c][j+1][:] (rows>=6400 zero)
// mma grid (32, 51): CTA tile M=144 (exactly 4 b's) x N=128, K=1024.
// Epilogue: masked per-b column max, per-c partial sums -> atomicAdd g_S.
// ============================================================================

static constexpr int NB  = 128;
static constexpr int DIM = 1024;
static constexpr int A_ROWS = 4608;           // 128 * 36
static constexpr int B_ROWS = 6400;           // 128 * 50
static constexpr int B_ROWS_PAD = 6528;       // + 128 zero rows (51 * 128)

__device__ __align__(16) __nv_bfloat16 g_A[A_ROWS * DIM];
__device__ __align__(16) __nv_bfloat16 g_B[B_ROWS_PAD * DIM];
__device__ float g_S[NB * NB];

// ---------------------------------------------------------------------------
__device__ __forceinline__ uint32_t smem_u32(const void* p) {
    uint32_t a;
    asm("{ .reg .u64 t; cvta.to.shared.u64 t, %1; cvt.u32.u64 %0, t; }" : "=r"(a) : "l"(p));
    return a;
}
__device__ __forceinline__ void cpa16(uint32_t dst, const void* src) {
    asm volatile("cp.async.cg.shared.global [%0], [%1], 16;" :: "r"(dst), "l"(src));
}
#define CPA_COMMIT() asm volatile("cp.async.commit_group;" ::: "memory")
#define CPA_WAIT1()  asm volatile("cp.async.wait_group 1;" ::: "memory")
#define CPA_WAIT0()  asm volatile("cp.async.wait_group 0;" ::: "memory")

__device__ __forceinline__ uint32_t lds32(uint32_t a) {
    uint32_t v;
    asm volatile("ld.shared.b32 %0, [%1];" : "=r"(v) : "r"(a));
    return v;
}
__device__ __forceinline__ void mma_bf16(float& d0, float& d1, float& d2, float& d3,
                                         uint32_t a0, uint32_t a1, uint32_t a2, uint32_t a3,
                                         uint32_t b0, uint32_t b1) {
    asm volatile(
        "mma.sync.aligned.m16n8k16.row.col.f32.bf16.bf16.f32 "
        "{%0,%1,%2,%3}, {%4,%5,%6,%7}, {%8,%9}, {%0,%1,%2,%3};"
        : "+f"(d0), "+f"(d1), "+f"(d2), "+f"(d3)
        : "r"(a0), "r"(a1), "r"(a2), "r"(a3), "r"(b0), "r"(b1));
}

// ---------------------------------------------------------------------------
// Stage 1: dense pack fp32 -> bf16 (one block per packed row) + zero g_S
// ---------------------------------------------------------------------------
__global__ void pack_kernel(const float* __restrict__ im, const float* __restrict__ sq) {
    const int row = blockIdx.x;
    const int tid = threadIdx.x;

    if (row < 16) {  // zero g_S (16 blocks x 256 threads x 4 floats = 16384)
        reinterpret_cast<float4*>(g_S)[row * 256 + tid] = make_float4(0.f, 0.f, 0.f, 0.f);
    }

    const float* src = nullptr;
    __nv_bfloat16* dst;
    if (row < A_ROWS) {
        int b = row / 36, i = row - b * 36;
        src = im + (size_t)(b * 37 + i + 1) * DIM;
        dst = g_A + (size_t)row * DIM;
    } else {
        int rb = row - A_ROWS;
        dst = g_B + (size_t)rb * DIM;
        if (rb < B_ROWS) {
            int c = rb / 50, j = rb - c * 50;
            src = sq + (size_t)(c * 53 + j + 1) * DIM;
        }
    }
    const int k = tid * 4;
    uint2 out;
    if (src) {
        float4 v = *reinterpret_cast<const float4*>(src + k);
        __nv_bfloat162 lo = __floats2bfloat162_rn(v.x, v.y);
        __nv_bfloat162 hi = __floats2bfloat162_rn(v.z, v.w);
        out.x = *reinterpret_cast<uint32_t*>(&lo);
        out.y = *reinterpret_cast<uint32_t*>(&hi);
    } else {
        out.x = 0u; out.y = 0u;
    }
    *reinterpret_cast<uint2*>(dst + k) = out;
}

// ---------------------------------------------------------------------------
// Stage 2: mma.sync GEMM (144x128 tile) + fused epilogue
// ---------------------------------------------------------------------------
// smem: stage s at s*21760: A 144 rows x 80B, B (at +11520) 128 rows x 80B
//       pairS[16] at 43520; epilogue red[144][67] f32 aliases offset 0 (38592B)
static constexpr int STAGE_BYTES = 21760;
static constexpr int ROW_BYTES   = 80;
static constexpr int B_SM_OFF    = 11520;
static constexpr int SM_PAIRS    = 43520;
static constexpr int NCH = 32;

__global__ __launch_bounds__(384)
void mma_kernel(const int* __restrict__ im_len, const int* __restrict__ s_len) {
    __shared__ __align__(16) char sm[43584];
    const uint32_t sb = smem_u32(sm);
    const int tid  = threadIdx.x;
    const int lane = tid & 31;
    const int wid  = tid >> 5;
    const int mt = blockIdx.x;          // M tile: b's 4mt..4mt+3, A rows 144*mt..
    const int nt = blockIdx.y;          // N tile: packed B rows 128*nt..

    const __nv_bfloat16* Ap = g_A + (size_t)mt * (144 * DIM);
    const __nv_bfloat16* Bp = g_B + (size_t)nt * (128 * DIM);

    auto load_stage = [&](int stage, int chunk) {
        const int k0 = chunk * 32;
        const uint32_t base = sb + stage * STAGE_BYTES;
        #pragma unroll
        for (int it = 0; it < 3; ++it) {
            int idx = tid + it * 384;
            if (idx < 576) {
                int row = idx >> 2, seg = idx & 3;
                cpa16(base + row * ROW_BYTES + seg * 16, Ap + row * DIM + k0 + seg * 8);
            } else if (idx < 1088) {
                int u = idx - 576;
                int row = u >> 2, seg = u & 3;
                cpa16(base + B_SM_OFF + row * ROW_BYTES + seg * 16, Bp + row * DIM + k0 + seg * 8);
            }
        }
    };

    // 12 warps: 3 (m) x 4 (n); warp tile 48 x 32
    const int wm = wid >> 2;        // 0..2
    const int wn = wid & 3;         // 0..3
    const int group = lane >> 2;    // 0..7
    const int tig   = lane & 3;     // 0..3
    const int mbase = wm * 48;
    const int nbase = wn * 32;

    float acc[3][4][4];
    #pragma unroll
    for (int mi = 0; mi < 3; ++mi)
        #pragma unroll
        for (int ni = 0; ni < 4; ++ni)
            #pragma unroll
            for (int q = 0; q < 4; ++q) acc[mi][ni][q] = 0.f;

    load_stage(0, 0); CPA_COMMIT();
    load_stage(1, 1); CPA_COMMIT();

    for (int ch = 0; ch < NCH; ++ch) {
        CPA_WAIT1();
        __syncthreads();
        const uint32_t As = sb + (ch & 1) * STAGE_BYTES;
        const uint32_t Bs = As + B_SM_OFF;
        #pragma unroll
        for (int kk = 0; kk < 2; ++kk) {
            const uint32_t kb = kk * 32;
            uint32_t a[3][4];
            #pragma unroll
            for (int mi = 0; mi < 3; ++mi) {
                uint32_t r0 = As + (mbase + mi * 16 + group) * ROW_BYTES + kb + tig * 4;
                uint32_t r1 = r0 + 8 * ROW_BYTES;
                a[mi][0] = lds32(r0);
                a[mi][1] = lds32(r1);
                a[mi][2] = lds32(r0 + 16);
                a[mi][3] = lds32(r1 + 16);
            }
            #pragma unroll
            for (int ni = 0; ni < 4; ++ni) {
                uint32_t rb = Bs + (nbase + ni * 8 + group) * ROW_BYTES + kb + tig * 4;
                uint32_t b0 = lds32(rb);
                uint32_t b1 = lds32(rb + 16);
                #pragma unroll
                for (int mi = 0; mi < 3; ++mi)
                    mma_bf16(acc[mi][ni][0], acc[mi][ni][1], acc[mi][ni][2], acc[mi][ni][3],
                             a[mi][0], a[mi][1], a[mi][2], a[mi][3], b0, b1);
            }
        }
        __syncthreads();
        if (ch + 2 < NCH) load_stage(ch & 1, ch + 2);
        CPA_COMMIT();
    }
    CPA_WAIT0();
    __syncthreads();

    // ---------------- epilogue ----------------
    float* red   = reinterpret_cast<float*>(sm);              // [144][67]
    float* pairS = reinterpret_cast<float*>(sm + SM_PAIRS);   // [4 b][4 c_local]

    // per-thread row validity (6 row positions)
    int  rowv[3][2];
    bool valv[3][2];
    #pragma unroll
    for (int mi = 0; mi < 3; ++mi)
        #pragma unroll
        for (int half = 0; half < 2; ++half) {
            int r = mbase + mi * 16 + group + half * 8;
            int bl = r / 36;
            rowv[mi][half] = r;
            valv[mi][half] = (r - bl * 36) < (__ldg(&im_len[mt * 4 + bl]) - 1);
        }

    const int n0 = nt * 128;
    #pragma unroll
    for (int h = 0; h < 2; ++h) {
        if (tid < 16) pairS[tid] = 0.f;
        if ((wn >> 1) == h) {   // warps owning columns [h*64, h*64+64)
            #pragma unroll
            for (int mi = 0; mi < 3; ++mi)
                #pragma unroll
                for (int half = 0; half < 2; ++half) {
                    const int r = rowv[mi][half];
                    const bool v = valv[mi][half];
                    #pragma unroll
                    for (int ni = 0; ni < 4; ++ni) {
                        int col = nbase + ni * 8 + tig * 2 - h * 64;
                        red[r * 67 + col]     = v ? acc[mi][ni][half * 2 + 0] : 0.f;
                        red[r * 67 + col + 1] = v ? acc[mi][ni][half * 2 + 1] : 0.f;
                    }
                }
        }
        __syncthreads();

        const int cbase = (n0 + h * 64) / 50;
        if (tid < 256) {
            const int bq = tid >> 6, colq = tid & 63;
            const int pc = n0 + h * 64 + colq;
            if (pc < B_ROWS) {
                const int c = pc / 50, j = pc - (pc / 50) * 50;
                if (j < __ldg(&s_len[c]) - 3) {
                    const float* colp = red + (bq * 36) * 67 + colq;
                    float m = colp[0];
                    #pragma unroll
                    for (int rr = 1; rr < 36; ++rr) m = fmaxf(m, colp[rr * 67]);
                    atomicAdd(&pairS[bq * 4 + (c - cbase)], m);
                }
            }
        }
        __syncthreads();
        if (tid < 16) {
            const int bq = tid >> 2, cl = tid & 3;
            const int c = cbase + cl;
            if (c < NB) atomicAdd(&g_S[(mt * 4 + bq) * NB + c], pairS[tid]);
        }
        __syncthreads();
    }
}

// ---------------------------------------------------------------------------
// Stage 3: hinge-loss reduction over S (128x128)
// ---------------------------------------------------------------------------
__global__ void loss_kernel(float* __restrict__ out) {
    __shared__ float diag[NB];
    __shared__ float wsum[8];
    const int tid = threadIdx.x;
    if (tid < NB) diag[tid] = g_S[tid * (NB + 1)];
    __syncthreads();
    float acc = 0.f;
    for (int idx = tid; idx < NB * NB; idx += 256) {
        int b = idx >> 7, c = idx & 127;
        if (b != c) {
            float sc = g_S[idx];
            acc += fmaxf(0.f, 0.2f + sc - diag[b]) + fmaxf(0.f, 0.2f + sc - diag[c]);
        }
    }
    #pragma unroll
    for (int o = 16; o; o >>= 1) acc += __shfl_xor_sync(0xffffffffu, acc, o);
    if ((tid & 31) == 0) wsum[tid >> 5] = acc;
    __syncthreads();
    if (tid < 8) {
        float v = wsum[tid];
        #pragma unroll
        for (int o = 4; o; o >>= 1) v += __shfl_xor_sync(0xffu, v, o);
        if (tid == 0) out[0] = v;
    }
}

// ---------------------------------------------------------------------------
extern "C" void kernel_launch(void* const* d_in, const int* in_sizes, int n_in,
                              void* d_out, int out_size) {
    (void)in_sizes; (void)n_in; (void)out_size;
    const float* im   = (const float*)d_in[0];
    const float* sq   = (const float*)d_in[1];
    const int* im_len = (const int*)d_in[2];
    const int* s_len  = (const int*)d_in[3];

    pack_kernel<<<A_ROWS + B_ROWS_PAD, 256>>>(im, sq);
    mma_kernel<<<dim3(32, 51), 384>>>(im_len, s_len);
    loss_kernel<<<1, 256>>>((float*)d_out);
}